// round 12
// baseline (speedup 1.0000x reference)
#include <cuda_runtime.h>

#define NN 100000
#define EE 1600000
#define HD 64
#define CC 40
#define BN_EPS 1e-5f
#define SCAN_NBLK ((NN + 1023) / 1024)   // 98

// ---------------- device scratch (static globals; no runtime allocation) ----------------
__device__ int   g_mode;          // 0 = edge_index int32, 1 = int64
__device__ int   g_edst[EE];
__device__ int   g_deg[NN];
__device__ int   g_off[NN];       // after scan3: global start offsets; after build: end offsets
__device__ int   g_srcs[EE];
__device__ int   g_bsum[SCAN_NBLK];
__device__ int   g_bpre[SCAN_NBLK];
__device__ __align__(16) float g_pre [NN * HD];   // layer-1 pre-activation
__device__ __align__(16) float g_act1[NN * HD];   // layer-2 pre-activation
__device__ float g_sums1[2 * HD];                 // layer-1 BN raw stats
__device__ float g_sums2[2 * HD];                 // layer-2 BN raw stats

// ---------------- init: zero counters/stats + edge dtype detection ----------------
__global__ void k_init(const int* __restrict__ p32) {
    int i = blockIdx.x * blockDim.x + threadIdx.x;
    if (i < NN) g_deg[i] = 0;
    if (i < 2 * HD) { g_sums1[i] = 0.f; g_sums2[i] = 0.f; }
    if (i == 0) {
        int allz = 1;
        for (int t = 0; t < 32; t++)
            if (p32[2 * t + 1] != 0) allz = 0;
        g_mode = allz;   // int64 data: high words of first 32 ids are all zero
    }
}

__global__ void k_hist(const int* __restrict__ p32) {
    int e = blockIdx.x * blockDim.x + threadIdx.x;
    if (e < EE) {
        int d = g_mode ? p32[2 * EE + 2 * e] : p32[EE + e];
        g_edst[e] = d;
        atomicAdd(&g_deg[d], 1);
    }
}

// ---- proven 3-phase grid scan (round 8) ----
__global__ void k_scan1() {
    __shared__ int ss[1024];
    int tid = threadIdx.x;
    int i = blockIdx.x * 1024 + tid;
    int v = (i < NN) ? g_deg[i] : 0;
    ss[tid] = v;
    __syncthreads();
#pragma unroll
    for (int d = 1; d < 1024; d <<= 1) {
        int t = (tid >= d) ? ss[tid - d] : 0;
        __syncthreads();
        ss[tid] += t;
        __syncthreads();
    }
    if (i < NN) g_off[i] = ss[tid] - v;
    if (tid == 1023) g_bsum[blockIdx.x] = ss[1023];
}

__global__ void k_scan2() {
    __shared__ int ss[128];
    int tid = threadIdx.x;
    int v = (tid < SCAN_NBLK) ? g_bsum[tid] : 0;
    ss[tid] = v;
    __syncthreads();
#pragma unroll
    for (int d = 1; d < 128; d <<= 1) {
        int t = (tid >= d) ? ss[tid - d] : 0;
        __syncthreads();
        ss[tid] += t;
        __syncthreads();
    }
    if (tid < SCAN_NBLK) g_bpre[tid] = ss[tid] - v;
}

__global__ void k_scan3() {
    int i = blockIdx.x * blockDim.x + threadIdx.x;
    if (i < NN) g_off[i] += g_bpre[i >> 10];
}

// scatter: atomic cursor directly on global g_off (returned old value = slot)
__global__ void k_build(const int* __restrict__ p32) {
    int e = blockIdx.x * blockDim.x + threadIdx.x;
    if (e < EE) {
        int s = g_mode ? p32[2 * e] : p32[e];
        int d = g_edst[e];
        int p = atomicAdd(&g_off[d], 1);
        g_srcs[p] = s;
    }
}

// ---------------- fused layer: gather-mean + dual GEMM + BN-stats epilogue ----------------
// MODE 0: in = Xext raw, out = g_pre, stats -> g_sums1.
// MODE 1: in = g_pre with BN1+ReLU (coeffs from g_sums1), out = g_act1, stats -> g_sums2.
__device__ __forceinline__ void xf_acc(float4& acc, float4 v,
                                       const float4& a4, const float4& b4, int mode) {
    if (mode) {
        v.x = fmaxf(fmaf(v.x, a4.x, b4.x), 0.f);
        v.y = fmaxf(fmaf(v.y, a4.y, b4.y), 0.f);
        v.z = fmaxf(fmaf(v.z, a4.z, b4.z), 0.f);
        v.w = fmaxf(fmaf(v.w, a4.w, b4.w), 0.f);
    }
    acc.x += v.x; acc.y += v.y; acc.z += v.z; acc.w += v.w;
}

template <int MODE>
__global__ void k_layer(const float* __restrict__ Xext,
                        const float* __restrict__ Wl, const float* __restrict__ bl,
                        const float* __restrict__ Wr,
                        const float* __restrict__ gamma, const float* __restrict__ beta) {
    __shared__ float xs[64 * 64];                  // [k][n] swizzled; reused for stats
    __shared__ __align__(16) float wsx[64 * 64];   // staging (gather rows), then weights
    __shared__ __align__(16) float sa[HD], sb[HD];
    int tid = threadIdx.x;
    int node0 = blockIdx.x * 64;
    const float* __restrict__ Xp  = MODE ? (const float*)g_pre : Xext;
    float* __restrict__       out = MODE ? (float*)g_act1 : (float*)g_pre;

    if (MODE) {
        if (tid < HD) {
            float mu  = g_sums1[tid] * (1.f / (float)NN);
            float var = g_sums1[HD + tid] * (1.f / (float)NN) - mu * mu;
            float a   = gamma[tid] * rsqrtf(var + BN_EPS);
            sa[tid] = a;
            sb[tid] = beta[tid] - mu * a;
        }
        __syncthreads();
    }

    // ---- gather-mean: 16 lanes/node (coalesced 256B rows), rows -> wsx [n][64] ----
    {
        const float4* __restrict__ in4 = (const float4*)Xp;
        int warp = tid >> 5, lane = tid & 31;
        int half = lane >> 4, c4 = lane & 15;
        float4 a4 = make_float4(1.f, 1.f, 1.f, 1.f);
        float4 b4 = make_float4(0.f, 0.f, 0.f, 0.f);
        if (MODE) {
            a4 = ((const float4*)sa)[c4];
            b4 = ((const float4*)sb)[c4];
        }
#pragma unroll
        for (int t = 0; t < 4; t++) {
            int n  = warp * 8 + t * 2 + half;
            int gn = node0 + n;
            float4 acc = make_float4(0.f, 0.f, 0.f, 0.f);
            if (gn < NN) {
                int d   = g_deg[gn];
                int off = g_off[gn] - d;        // g_off = end offsets after k_build
                int j = 0;
                for (; j + 4 <= d; j += 4) {
                    int s0 = g_srcs[off + j];
                    int s1 = g_srcs[off + j + 1];
                    int s2 = g_srcs[off + j + 2];
                    int s3 = g_srcs[off + j + 3];
                    float4 v0 = __ldg(&in4[(size_t)s0 * 16 + c4]);
                    float4 v1 = __ldg(&in4[(size_t)s1 * 16 + c4]);
                    float4 v2 = __ldg(&in4[(size_t)s2 * 16 + c4]);
                    float4 v3 = __ldg(&in4[(size_t)s3 * 16 + c4]);
                    xf_acc(acc, v0, a4, b4, MODE);
                    xf_acc(acc, v1, a4, b4, MODE);
                    xf_acc(acc, v2, a4, b4, MODE);
                    xf_acc(acc, v3, a4, b4, MODE);
                }
                for (; j < d; j++) {
                    float4 v0 = __ldg(&in4[(size_t)g_srcs[off + j] * 16 + c4]);
                    xf_acc(acc, v0, a4, b4, MODE);
                }
                float inv = 1.f / (float)max(d, 1);
                acc.x *= inv; acc.y *= inv; acc.z *= inv; acc.w *= inv;
            }
            ((float4*)wsx)[n * 16 + c4] = acc;
        }
    }
    __syncthreads();

    // re-layout staging rows into swizzled k-major xs
    for (int idx = tid; idx < 4096; idx += 256) {
        int n = idx >> 6, k = idx & 63;
        xs[k * 64 + (n ^ ((k & 15) << 2))] = wsx[idx];
    }
    __syncthreads();
    // load Wl over the staging area
    for (int idx = tid; idx < 4096; idx += 256) {
        int c = idx >> 6, k = idx & 63;
        wsx[k * 64 + (c ^ ((k & 15) << 2))] = Wl[idx];
    }
    __syncthreads();

    int c0 = (tid & 15) * 4;
    int n0 = (tid >> 4) * 4;

    float acc[4][4];
#pragma unroll
    for (int j = 0; j < 4; j++) {
        float b = __ldg(&bl[c0 + j]);
#pragma unroll
        for (int i = 0; i < 4; i++) acc[i][j] = b;
    }

    // GEMM phase 0: agg tile x Wl
#pragma unroll 8
    for (int k = 0; k < 64; k++) {
        int sw = (k & 15) << 2;
        float4 wv = *reinterpret_cast<const float4*>(&wsx[k * 64 + (c0 ^ sw)]);
        float4 xv = *reinterpret_cast<const float4*>(&xs[k * 64 + (n0 ^ sw)]);
        float wr[4] = {wv.x, wv.y, wv.z, wv.w};
        float xr[4] = {xv.x, xv.y, xv.z, xv.w};
#pragma unroll
        for (int i = 0; i < 4; i++)
#pragma unroll
            for (int j = 0; j < 4; j++)
                acc[i][j] += xr[i] * wr[j];
    }
    __syncthreads();

    // phase 1: root tile (+BN for MODE 1) x Wr
    for (int idx = tid; idx < 4096; idx += 256) {
        int n = idx >> 6, k = idx & 63;
        int gn = node0 + n;
        float v = (gn < NN) ? Xp[(size_t)gn * HD + k] : 0.f;
        if (MODE) v = fmaxf(fmaf(v, sa[k], sb[k]), 0.f);
        xs[k * 64 + (n ^ ((k & 15) << 2))] = v;
    }
    for (int idx = tid; idx < 4096; idx += 256) {
        int c = idx >> 6, k = idx & 63;
        wsx[k * 64 + (c ^ ((k & 15) << 2))] = Wr[idx];
    }
    __syncthreads();

#pragma unroll 8
    for (int k = 0; k < 64; k++) {
        int sw = (k & 15) << 2;
        float4 wv = *reinterpret_cast<const float4*>(&wsx[k * 64 + (c0 ^ sw)]);
        float4 xv = *reinterpret_cast<const float4*>(&xs[k * 64 + (n0 ^ sw)]);
        float wr[4] = {wv.x, wv.y, wv.z, wv.w};
        float xr[4] = {xv.x, xv.y, xv.z, xv.w};
#pragma unroll
        for (int i = 0; i < 4; i++)
#pragma unroll
            for (int j = 0; j < 4; j++)
                acc[i][j] += xr[i] * wr[j];
    }
    __syncthreads();   // xs about to be reused for stats

    // store output
#pragma unroll
    for (int i = 0; i < 4; i++) {
        int gn = node0 + n0 + i;
        if (gn < NN) {
            float4 v = make_float4(acc[i][0], acc[i][1], acc[i][2], acc[i][3]);
            *reinterpret_cast<float4*>(&out[(size_t)gn * HD + c0]) = v;
        }
    }

    // BN stats epilogue
    float s[4] = {0.f, 0.f, 0.f, 0.f};
    float q[4] = {0.f, 0.f, 0.f, 0.f};
#pragma unroll
    for (int i = 0; i < 4; i++) {
        if (node0 + n0 + i < NN) {
#pragma unroll
            for (int j = 0; j < 4; j++) {
                float v = acc[i][j];
                s[j] += v; q[j] += v * v;
            }
        }
    }
    float* rs = xs;            // 16 x 64
    float* rq = xs + 1024;     // 16 x 64
    int grp = tid >> 4;
#pragma unroll
    for (int j = 0; j < 4; j++) {
        rs[grp * 64 + c0 + j] = s[j];
        rq[grp * 64 + c0 + j] = q[j];
    }
    __syncthreads();
    if (tid < 64) {
        float ts = 0.f, tq = 0.f;
#pragma unroll
        for (int g = 0; g < 16; g++) {
            ts += rs[g * 64 + tid];
            tq += rq[g * 64 + tid];
        }
        float* dst = MODE ? g_sums2 : g_sums1;
        atomicAdd(&dst[tid], ts);
        atomicAdd(&dst[HD + tid], tq);
    }
}

// ---------------- decoder: h = relu(bn2(g_act1)) -> hout ; logits = h@Wd^T + bd ----------------
__global__ void k_dec(const float* __restrict__ Wd, const float* __restrict__ bd,
                      const float* __restrict__ gamma, const float* __restrict__ beta,
                      float* __restrict__ hout, float* __restrict__ logits) {
    __shared__ float wd[CC * 65];
    __shared__ float hs[128 * 65];
    __shared__ float sa[HD], sb[HD];
    int tid = threadIdx.x;

    if (tid < HD) {
        float mu  = g_sums2[tid] * (1.f / (float)NN);
        float var = g_sums2[HD + tid] * (1.f / (float)NN) - mu * mu;
        float a   = gamma[tid] * rsqrtf(var + BN_EPS);
        sa[tid] = a;
        sb[tid] = beta[tid] - mu * a;
    }
    for (int idx = tid; idx < CC * HD; idx += 256) {
        int c = idx / HD, k = idx % HD;
        wd[c * 65 + k] = Wd[idx];
    }
    __syncthreads();

    int node0 = blockIdx.x * 128;
    for (int idx = tid; idx < 128 * HD; idx += 256) {
        int n = idx >> 6, k = idx & 63;
        int gn = node0 + n;
        float y = 0.f;
        if (gn < NN) {
            float v = g_act1[(size_t)gn * HD + k];
            y = fmaxf(fmaf(v, sa[k], sb[k]), 0.f);
            hout[(size_t)gn * HD + k] = y;
        }
        hs[n * 65 + k] = y;
    }
    __syncthreads();

    int c0 = (tid & 3) * 10;
    int n0 = (tid >> 2) * 2;

    float acc[2][10];
#pragma unroll
    for (int j = 0; j < 10; j++) {
        float b = __ldg(&bd[c0 + j]);
        acc[0][j] = b; acc[1][j] = b;
    }
#pragma unroll 4
    for (int k = 0; k < 64; k++) {
        float w[10];
#pragma unroll
        for (int j = 0; j < 10; j++) w[j] = wd[(c0 + j) * 65 + k];
        float a0 = hs[n0 * 65 + k];
        float a1 = hs[(n0 + 1) * 65 + k];
#pragma unroll
        for (int j = 0; j < 10; j++) {
            acc[0][j] += a0 * w[j];
            acc[1][j] += a1 * w[j];
        }
    }
#pragma unroll
    for (int i = 0; i < 2; i++) {
        int gn = node0 + n0 + i;
        if (gn < NN) {
#pragma unroll
            for (int j = 0; j < 10; j++)
                logits[(size_t)gn * CC + c0 + j] = acc[i][j];
        }
    }
}

// ---------------- launcher: ONLY kernel launches (9 total) ----------------
extern "C" void kernel_launch(void* const* d_in, const int* in_sizes, int n_in,
                              void* d_out, int out_size) {
    const float* x   = (const float*)d_in[0];
    const int*   ei  = (const int*)d_in[1];
    const float* W1l = (const float*)d_in[2];
    const float* b1l = (const float*)d_in[3];
    const float* W1r = (const float*)d_in[4];
    const float* g1  = (const float*)d_in[5];
    const float* be1 = (const float*)d_in[6];
    const float* W2l = (const float*)d_in[7];
    const float* b2l = (const float*)d_in[8];
    const float* W2r = (const float*)d_in[9];
    const float* g2  = (const float*)d_in[10];
    const float* be2 = (const float*)d_in[11];
    const float* Wd  = (const float*)d_in[12];
    const float* bd  = (const float*)d_in[13];

    float* outp   = (float*)d_out;
    float* logits = outp;                       // [N, C]
    float* hout   = outp + (size_t)NN * CC;     // [N, H]

    // CSR build (proven round-8 path)
    k_init<<<(NN + 255) / 256, 256>>>(ei);
    k_hist<<<(EE + 255) / 256, 256>>>(ei);
    k_scan1<<<SCAN_NBLK, 1024>>>();
    k_scan2<<<1, 128>>>();
    k_scan3<<<(NN + 255) / 256, 256>>>();
    k_build<<<(EE + 255) / 256, 256>>>(ei);

    // Layers (fused gather + dual GEMM + BN stats)
    k_layer<0><<<(NN + 63) / 64, 256>>>(x, W1l, b1l, W1r, nullptr, nullptr);
    k_layer<1><<<(NN + 63) / 64, 256>>>(nullptr, W2l, b2l, W2r, g1, be1);

    // Decoder
    k_dec<<<(NN + 127) / 128, 256>>>(Wd, bd, g2, be2, hout, logits);
}

// round 13
// speedup vs baseline: 1.1051x; 1.1051x over previous
#include <cuda_runtime.h>
#include <cuda_fp16.h>

#define NN 100000
#define EE 1600000
#define HD 64
#define CC 40
#define BN_EPS 1e-5f
#define SCAN_NBLK ((NN + 1023) / 1024)   // 98

// ---------------- device scratch (static globals; no runtime allocation) ----------------
__device__ int   g_mode;          // 0 = edge_index int32, 1 = int64
__device__ int   g_edst[EE];
__device__ int   g_deg[NN];
__device__ int   g_off[NN];       // after scan3: start offsets; after build: end offsets
__device__ int   g_srcs[EE];
__device__ int   g_bsum[SCAN_NBLK];
__device__ int   g_bpre[SCAN_NBLK];
__device__ __align__(16) __half g_x16 [NN * HD];  // fp16 copy of x (gather source, L1)
__device__ __align__(16) __half g_a16 [NN * HD];  // fp16 relu(bn1(pre)) (gather source, L2)
__device__ __align__(16) float g_agg [NN * HD];
__device__ __align__(16) float g_pre [NN * HD];   // layer-1 pre-activation (fp32)
__device__ __align__(16) float g_act1[NN * HD];   // layer-2 pre-activation (fp32)
__device__ float g_sums1[2 * HD];                 // layer-1 BN raw stats
__device__ float g_sums2[2 * HD];                 // layer-2 BN raw stats

// ---------------- init: zero counters/stats, detect dtype, convert x -> fp16 ----------------
__global__ void k_init(const int* __restrict__ p32, const float* __restrict__ x) {
    int i = blockIdx.x * blockDim.x + threadIdx.x;
    if (i < NN * HD / 2) {
        float2 v = ((const float2*)x)[i];
        ((__half2*)g_x16)[i] = __float22half2_rn(v);
    }
    if (i < NN) g_deg[i] = 0;
    if (i < 2 * HD) { g_sums1[i] = 0.f; g_sums2[i] = 0.f; }
    if (i == 0) {
        int allz = 1;
        for (int t = 0; t < 32; t++)
            if (p32[2 * t + 1] != 0) allz = 0;
        g_mode = allz;   // int64 data: high words of first 32 ids are all zero
    }
}

__global__ void k_hist(const int* __restrict__ p32) {
    int e = blockIdx.x * blockDim.x + threadIdx.x;
    if (e < EE) {
        int d = g_mode ? p32[2 * EE + 2 * e] : p32[EE + e];
        g_edst[e] = d;
        atomicAdd(&g_deg[d], 1);
    }
}

// ---- proven 3-phase grid scan ----
__global__ void k_scan1() {
    __shared__ int ss[1024];
    int tid = threadIdx.x;
    int i = blockIdx.x * 1024 + tid;
    int v = (i < NN) ? g_deg[i] : 0;
    ss[tid] = v;
    __syncthreads();
#pragma unroll
    for (int d = 1; d < 1024; d <<= 1) {
        int t = (tid >= d) ? ss[tid - d] : 0;
        __syncthreads();
        ss[tid] += t;
        __syncthreads();
    }
    if (i < NN) g_off[i] = ss[tid] - v;
    if (tid == 1023) g_bsum[blockIdx.x] = ss[1023];
}

__global__ void k_scan2() {
    __shared__ int ss[128];
    int tid = threadIdx.x;
    int v = (tid < SCAN_NBLK) ? g_bsum[tid] : 0;
    ss[tid] = v;
    __syncthreads();
#pragma unroll
    for (int d = 1; d < 128; d <<= 1) {
        int t = (tid >= d) ? ss[tid - d] : 0;
        __syncthreads();
        ss[tid] += t;
        __syncthreads();
    }
    if (tid < SCAN_NBLK) g_bpre[tid] = ss[tid] - v;
}

__global__ void k_scan3() {
    int i = blockIdx.x * blockDim.x + threadIdx.x;
    if (i < NN) g_off[i] += g_bpre[i >> 10];
}

// scatter: atomic cursor directly on global g_off (returned old value = slot)
__global__ void k_build(const int* __restrict__ p32) {
    int e = blockIdx.x * blockDim.x + threadIdx.x;
    if (e < EE) {
        int s = g_mode ? p32[2 * e] : p32[e];
        int d = g_edst[e];
        int p = atomicAdd(&g_off[d], 1);
        g_srcs[p] = s;
    }
}

// ---------------- mean aggregation: 8 lanes/node, fp16 rows (128B), fp32 accum ----------------
// L = 0: gather from g_x16.  L = 1: gather from g_a16 (BN1+ReLU already applied).
__device__ __forceinline__ void h8_acc(float* a, uint4 v) {
    float2 f0 = __half22float2(*(__half2*)&v.x);
    float2 f1 = __half22float2(*(__half2*)&v.y);
    float2 f2 = __half22float2(*(__half2*)&v.z);
    float2 f3 = __half22float2(*(__half2*)&v.w);
    a[0] += f0.x; a[1] += f0.y; a[2] += f1.x; a[3] += f1.y;
    a[4] += f2.x; a[5] += f2.y; a[6] += f3.x; a[7] += f3.y;
}

template <int L>
__global__ void k_agg() {
    const uint4* __restrict__ in4 = L ? (const uint4*)g_a16 : (const uint4*)g_x16;
    int node = blockIdx.x * 16 + (threadIdx.x >> 3);
    int c8   = threadIdx.x & 7;           // 8 lanes/node; 16B (8 halves) per lane
    if (node >= NN) return;

    int d   = g_deg[node];
    int off = g_off[node] - d;            // g_off = end offsets after k_build
    float acc[8] = {0.f, 0.f, 0.f, 0.f, 0.f, 0.f, 0.f, 0.f};

    int j = 0;
    for (; j + 4 <= d; j += 4) {
        int s0 = g_srcs[off + j];
        int s1 = g_srcs[off + j + 1];
        int s2 = g_srcs[off + j + 2];
        int s3 = g_srcs[off + j + 3];
        uint4 v0 = __ldg(&in4[(size_t)s0 * 8 + c8]);
        uint4 v1 = __ldg(&in4[(size_t)s1 * 8 + c8]);
        uint4 v2 = __ldg(&in4[(size_t)s2 * 8 + c8]);
        uint4 v3 = __ldg(&in4[(size_t)s3 * 8 + c8]);
        h8_acc(acc, v0); h8_acc(acc, v1); h8_acc(acc, v2); h8_acc(acc, v3);
    }
    for (; j < d; j++) {
        uint4 v0 = __ldg(&in4[(size_t)g_srcs[off + j] * 8 + c8]);
        h8_acc(acc, v0);
    }

    float inv = 1.f / (float)max(d, 1);
    float4* outp = (float4*)&g_agg[(size_t)node * HD + c8 * 8];
    outp[0] = make_float4(acc[0] * inv, acc[1] * inv, acc[2] * inv, acc[3] * inv);
    outp[1] = make_float4(acc[4] * inv, acc[5] * inv, acc[6] * inv, acc[7] * inv);
}

// ---------------- fused dual GEMM + BN-stats epilogue (round-9 proven) ----------------
// MODE 0: X = Xext raw, out = g_pre, stats -> g_sums1.
// MODE 1: X = g_pre with BN1+ReLU (coeffs from g_sums1), out = g_act1, stats -> g_sums2.
template <int MODE>
__global__ void k_gemm(const float* __restrict__ Xext,
                       const float* __restrict__ Wl, const float* __restrict__ bl,
                       const float* __restrict__ Wr,
                       const float* __restrict__ gamma, const float* __restrict__ beta) {
    __shared__ float xs[64 * 64];   // [k][n] swizzled ; reused for stats reduction
    __shared__ float ws[64 * 64];   // [k][c] swizzled
    __shared__ float sa[HD], sb[HD];
    int tid = threadIdx.x;
    int node0 = blockIdx.x * 64;
    const float* __restrict__ Xp  = MODE ? (const float*)g_pre : Xext;
    float* __restrict__       out = MODE ? (float*)g_act1 : (float*)g_pre;

    int c0 = (tid & 15) * 4;
    int n0 = (tid >> 4) * 4;

    float acc[4][4];
#pragma unroll
    for (int j = 0; j < 4; j++) {
        float b = __ldg(&bl[c0 + j]);
#pragma unroll
        for (int i = 0; i < 4; i++) acc[i][j] = b;
    }

#pragma unroll
    for (int ph = 0; ph < 2; ph++) {
        const float* __restrict__ src = ph ? Xp : (const float*)g_agg;
        const float* __restrict__ W   = ph ? Wr : Wl;
        const bool bn = MODE && (ph == 1);

        if (MODE && ph == 0 && tid < HD) {   // BN1 coeffs; visibility covered by sync below
            float mu  = g_sums1[tid] * (1.f / (float)NN);
            float var = g_sums1[HD + tid] * (1.f / (float)NN) - mu * mu;
            float a   = gamma[tid] * rsqrtf(var + BN_EPS);
            sa[tid] = a;
            sb[tid] = beta[tid] - mu * a;
        }

        for (int idx = tid; idx < 4096; idx += 256) {
            int n = idx >> 6, k = idx & 63;
            int gn = node0 + n;
            float v = (gn < NN) ? src[(size_t)gn * HD + k] : 0.f;
            if (bn) v = fmaxf(fmaf(v, sa[k], sb[k]), 0.f);
            xs[k * 64 + (n ^ ((k & 15) << 2))] = v;
        }
        for (int idx = tid; idx < 4096; idx += 256) {
            int c = idx >> 6, k = idx & 63;
            ws[k * 64 + (c ^ ((k & 15) << 2))] = W[idx];
        }
        __syncthreads();

#pragma unroll 8
        for (int k = 0; k < 64; k++) {
            int sw = (k & 15) << 2;
            float4 wv = *reinterpret_cast<const float4*>(&ws[k * 64 + (c0 ^ sw)]);
            float4 xv = *reinterpret_cast<const float4*>(&xs[k * 64 + (n0 ^ sw)]);
            float wr[4] = {wv.x, wv.y, wv.z, wv.w};
            float xr[4] = {xv.x, xv.y, xv.z, xv.w};
#pragma unroll
            for (int i = 0; i < 4; i++)
#pragma unroll
                for (int j = 0; j < 4; j++)
                    acc[i][j] += xr[i] * wr[j];
        }
        __syncthreads();
    }

    // store output
#pragma unroll
    for (int i = 0; i < 4; i++) {
        int gn = node0 + n0 + i;
        if (gn < NN) {
            float4 v = make_float4(acc[i][0], acc[i][1], acc[i][2], acc[i][3]);
            *reinterpret_cast<float4*>(&out[(size_t)gn * HD + c0]) = v;
        }
    }

    // BN stats epilogue
    float s[4] = {0.f, 0.f, 0.f, 0.f};
    float q[4] = {0.f, 0.f, 0.f, 0.f};
#pragma unroll
    for (int i = 0; i < 4; i++) {
        if (node0 + n0 + i < NN) {
#pragma unroll
            for (int j = 0; j < 4; j++) {
                float v = acc[i][j];
                s[j] += v; q[j] += v * v;
            }
        }
    }
    float* rs = xs;            // 16 x 64
    float* rq = xs + 1024;     // 16 x 64
    int grp = tid >> 4;
#pragma unroll
    for (int j = 0; j < 4; j++) {
        rs[grp * 64 + c0 + j] = s[j];
        rq[grp * 64 + c0 + j] = q[j];
    }
    __syncthreads();
    if (tid < 64) {
        float ts = 0.f, tq = 0.f;
#pragma unroll
        for (int g = 0; g < 16; g++) {
            ts += rs[g * 64 + tid];
            tq += rq[g * 64 + tid];
        }
        float* dst = MODE ? g_sums2 : g_sums1;
        atomicAdd(&dst[tid], ts);
        atomicAdd(&dst[HD + tid], tq);
    }
}

// ---------------- conv1: act16 = fp16(relu(bn1(g_pre))) ----------------
__global__ void k_conv1(const float* __restrict__ gamma, const float* __restrict__ beta) {
    __shared__ float sa[HD], sb[HD];
    int tid = threadIdx.x;
    if (tid < HD) {
        float mu  = g_sums1[tid] * (1.f / (float)NN);
        float var = g_sums1[HD + tid] * (1.f / (float)NN) - mu * mu;
        float a   = gamma[tid] * rsqrtf(var + BN_EPS);
        sa[tid] = a;
        sb[tid] = beta[tid] - mu * a;
    }
    __syncthreads();
    int i = blockIdx.x * blockDim.x + tid;
    if (i < NN * HD / 2) {
        float2 v = ((const float2*)g_pre)[i];
        int ch = (2 * i) & 63;
        float y0 = fmaxf(fmaf(v.x, sa[ch],     sb[ch]),     0.f);
        float y1 = fmaxf(fmaf(v.y, sa[ch + 1], sb[ch + 1]), 0.f);
        ((__half2*)g_a16)[i] = __float22half2_rn(make_float2(y0, y1));
    }
}

// ---------------- decoder: h = relu(bn2(g_act1)) -> hout ; logits = h@Wd^T + bd ----------------
__global__ void k_dec(const float* __restrict__ Wd, const float* __restrict__ bd,
                      const float* __restrict__ gamma, const float* __restrict__ beta,
                      float* __restrict__ hout, float* __restrict__ logits) {
    __shared__ float wd[CC * 65];
    __shared__ float hs[128 * 65];
    __shared__ float sa[HD], sb[HD];
    int tid = threadIdx.x;

    if (tid < HD) {
        float mu  = g_sums2[tid] * (1.f / (float)NN);
        float var = g_sums2[HD + tid] * (1.f / (float)NN) - mu * mu;
        float a   = gamma[tid] * rsqrtf(var + BN_EPS);
        sa[tid] = a;
        sb[tid] = beta[tid] - mu * a;
    }
    for (int idx = tid; idx < CC * HD; idx += 256) {
        int c = idx / HD, k = idx % HD;
        wd[c * 65 + k] = Wd[idx];
    }
    __syncthreads();

    int node0 = blockIdx.x * 128;
    for (int idx = tid; idx < 128 * HD; idx += 256) {
        int n = idx >> 6, k = idx & 63;
        int gn = node0 + n;
        float y = 0.f;
        if (gn < NN) {
            float v = g_act1[(size_t)gn * HD + k];
            y = fmaxf(fmaf(v, sa[k], sb[k]), 0.f);
            hout[(size_t)gn * HD + k] = y;
        }
        hs[n * 65 + k] = y;
    }
    __syncthreads();

    int c0 = (tid & 3) * 10;
    int n0 = (tid >> 2) * 2;

    float acc[2][10];
#pragma unroll
    for (int j = 0; j < 10; j++) {
        float b = __ldg(&bd[c0 + j]);
        acc[0][j] = b; acc[1][j] = b;
    }
#pragma unroll 4
    for (int k = 0; k < 64; k++) {
        float w[10];
#pragma unroll
        for (int j = 0; j < 10; j++) w[j] = wd[(c0 + j) * 65 + k];
        float a0 = hs[n0 * 65 + k];
        float a1 = hs[(n0 + 1) * 65 + k];
#pragma unroll
        for (int j = 0; j < 10; j++) {
            acc[0][j] += a0 * w[j];
            acc[1][j] += a1 * w[j];
        }
    }
#pragma unroll
    for (int i = 0; i < 2; i++) {
        int gn = node0 + n0 + i;
        if (gn < NN) {
#pragma unroll
            for (int j = 0; j < 10; j++)
                logits[(size_t)gn * CC + c0 + j] = acc[i][j];
        }
    }
}

// ---------------- launcher: ONLY kernel launches (12 total) ----------------
extern "C" void kernel_launch(void* const* d_in, const int* in_sizes, int n_in,
                              void* d_out, int out_size) {
    const float* x   = (const float*)d_in[0];
    const int*   ei  = (const int*)d_in[1];
    const float* W1l = (const float*)d_in[2];
    const float* b1l = (const float*)d_in[3];
    const float* W1r = (const float*)d_in[4];
    const float* g1  = (const float*)d_in[5];
    const float* be1 = (const float*)d_in[6];
    const float* W2l = (const float*)d_in[7];
    const float* b2l = (const float*)d_in[8];
    const float* W2r = (const float*)d_in[9];
    const float* g2  = (const float*)d_in[10];
    const float* be2 = (const float*)d_in[11];
    const float* Wd  = (const float*)d_in[12];
    const float* bd  = (const float*)d_in[13];

    float* outp   = (float*)d_out;
    float* logits = outp;                       // [N, C]
    float* hout   = outp + (size_t)NN * CC;     // [N, H]

    // CSR build + x -> fp16
    k_init<<<(NN * HD / 2 + 255) / 256, 256>>>(ei, x);
    k_hist<<<(EE + 255) / 256, 256>>>(ei);
    k_scan1<<<SCAN_NBLK, 1024>>>();
    k_scan2<<<1, 128>>>();
    k_scan3<<<(NN + 255) / 256, 256>>>();
    k_build<<<(EE + 255) / 256, 256>>>(ei);

    // Layer 1: gather(fp16 x) -> dual GEMM (+stats)
    k_agg<0><<<(NN + 15) / 16, 128>>>();
    k_gemm<0><<<(NN + 63) / 64, 256>>>(x, W1l, b1l, W1r, nullptr, nullptr);

    // act16 = fp16(relu(bn1(pre)))
    k_conv1<<<(NN * HD / 2 + 255) / 256, 256>>>(g1, be1);

    // Layer 2: gather(fp16 act) -> dual GEMM (bn1 on fp32 root path, +stats)
    k_agg<1><<<(NN + 15) / 16, 128>>>();
    k_gemm<1><<<(NN + 63) / 64, 256>>>(nullptr, W2l, b2l, W2r, g1, be1);

    // Decoder
    k_dec<<<(NN + 127) / 128, 256>>>(Wd, bd, g2, be2, hout, logits);
}